// round 1
// baseline (speedup 1.0000x reference)
#include <cuda_runtime.h>

// GARCH-LSTM fused cell. B rows, H=16 hidden.
// Persistent grid-stride kernel: lane handles fixed h = tid&15, coefficients in
// registers, loop over batch. sigmoid(x) = 0.5 + 0.5*tanh(x/2) with the 0.5
// pre-folded into the coefficients -> 4 MUFU.TANH per lane per element.

__device__ __forceinline__ float fast_tanh(float x) {
    float r;
    asm("tanh.approx.f32 %0, %1;" : "=f"(r) : "f"(x));
    return r;
}

__global__ void __launch_bounds__(256)
garch_lstm_kernel(
    const float* __restrict__ eps,
    const float* __restrict__ sigma2,
    const float* __restrict__ c_prev,
    const float* __restrict__ Wf_w, const float* __restrict__ Wf_b,
    const float* __restrict__ Uf_w, const float* __restrict__ Uf_b,
    const float* __restrict__ Wi_w, const float* __restrict__ Wi_b,
    const float* __restrict__ Ui_w, const float* __restrict__ Ui_b,
    const float* __restrict__ Wc_w, const float* __restrict__ Wc_b,
    const float* __restrict__ Uc_w, const float* __restrict__ Uc_b,
    const float* __restrict__ b_f, const float* __restrict__ b_i,
    const float* __restrict__ b_c,
    const float* __restrict__ w,
    const float* __restrict__ garch_w,
    const float* __restrict__ garch_b,
    float* __restrict__ out, int B)
{
    const int h = threadIdx.x & 15;

    // Hoist all per-h coefficients into registers once (broadcast L1 hits).
    // Pre-scale by 0.5 for the tanh-based sigmoid identity.
    const float Af = 0.5f * __ldg(Wf_w + h);
    const float Bf = 0.5f * __ldg(Uf_w + h);
    const float Cf = 0.5f * (__ldg(Wf_b + h) + __ldg(Uf_b + h) + __ldg(b_f));
    const float Ai = 0.5f * __ldg(Wi_w + h);
    const float Bi = 0.5f * __ldg(Ui_w + h);
    const float Ci = 0.5f * (__ldg(Wi_b + h) + __ldg(Ui_b + h) + __ldg(b_i));
    const float Ac = 0.5f * __ldg(Wc_w + h);
    const float Bc = 0.5f * __ldg(Uc_w + h);
    const float Cc = 0.5f * (__ldg(Wc_b + h) + __ldg(Uc_b + h) + __ldg(b_c));

    const float gw0 = __ldg(garch_w + 0);
    const float gw1 = __ldg(garch_w + 1);
    const float gw2 = __ldg(garch_w + 2);
    const float gw3 = __ldg(garch_w + 3);
    const float gb  = __ldg(garch_b);
    const float wv  = __ldg(w) * (1.0f / 16.0f);   // fold the mean's 1/16

    float* __restrict__ out_sig = out;       // sigma2_t : B floats
    float* __restrict__ out_c   = out + B;   // c_t      : B*16 floats

    int b = (blockIdx.x * blockDim.x + threadIdx.x) >> 4;
    const int stride = (gridDim.x * blockDim.x) >> 4;

    #pragma unroll 2
    for (; b < B; b += stride) {
        const float e  = __ldg(eps + b);
        const float s  = __ldg(sigma2 + b);
        const float cp = __ldg(c_prev + b * 16 + h);

        const float tf = fast_tanh(fmaf(e, Af, fmaf(s, Bf, Cf)));
        const float ti = fast_tanh(fmaf(e, Ai, fmaf(s, Bi, Ci)));
        const float tc = fast_tanh(fmaf(e, Ac, fmaf(s, Bc, Cc)));

        const float f_t   = fmaf(0.5f, tf, 0.5f);
        const float i_t   = fmaf(0.5f, ti, 0.5f);
        const float c_hat = fmaf(0.5f, tc, 0.5f);

        const float c = fmaf(f_t, cp, i_t * c_hat);
        out_c[b * 16 + h] = c;

        float th = fast_tanh(c);
        th += __shfl_xor_sync(0xffffffffu, th, 1);
        th += __shfl_xor_sync(0xffffffffu, th, 2);
        th += __shfl_xor_sync(0xffffffffu, th, 4);
        th += __shfl_xor_sync(0xffffffffu, th, 8);

        if (h == 0) {
            const float e2 = e * e;
            float o = fmaf(gw1, e2, fmaf(gw3, s, gw0 + gb));
            if (e < 0.0f) o = fmaf(gw2, e2, o);
            out_sig[b] = o * fmaf(wv, th, 1.0f);
        }
    }
}

extern "C" void kernel_launch(void* const* d_in, const int* in_sizes, int n_in,
                              void* d_out, int out_size) {
    // Two plausible input orderings:
    //  dict order (setup_inputs):     ... idx7 = Wi_w (size 16)
    //  signature order (reference):   ... idx7 = b_f  (size 1)
    const float* p[21];
    if (n_in >= 21 && in_sizes[7] == 1) {
        // reference-signature order
        const int map[21] = {0, 1, 2,
                             3, 4, 5, 6,      // Wf_w Wf_b Uf_w Uf_b
                             8, 9, 10, 11,    // Wi_w Wi_b Ui_w Ui_b
                             13, 14, 15, 16,  // Wc_w Wc_b Uc_w Uc_b
                             7, 12, 17,       // b_f b_i b_c
                             18, 19, 20};     // w garch_w garch_b
        for (int i = 0; i < 21; i++) p[i] = (const float*)d_in[map[i]];
    } else {
        // setup_inputs dict order
        for (int i = 0; i < 21; i++) p[i] = (const float*)d_in[i];
    }

    const int B = in_sizes[0];
    float* out = (float*)d_out;

    // 2048 blocks x 256 threads -> 32768 (b)-slots -> exactly B/32768 iterations
    garch_lstm_kernel<<<2048, 256>>>(
        p[0], p[1], p[2],
        p[3], p[4], p[5], p[6],
        p[7], p[8], p[9], p[10],
        p[11], p[12], p[13], p[14],
        p[15], p[16], p[17],
        p[18], p[19], p[20],
        out, B);
}

// round 2
// speedup vs baseline: 2.0310x; 2.0310x over previous
#include <cuda_runtime.h>

// GARCH-LSTM fused cell. B rows, H=16.
// Thread owns 4 h-values of one row (lane&3 = h-group): float4 c_prev/c_t,
// 2-level shfl reduction, 36 loop-invariant coefficient registers.
// sigmoid(x) = 0.5 + 0.5*tanh(x/2), 0.5 pre-folded into coefficients.

__device__ __forceinline__ float fast_tanh(float x) {
    float r;
    asm("tanh.approx.f32 %0, %1;" : "=f"(r) : "f"(x));
    return r;
}

__global__ void __launch_bounds__(128)
garch_lstm_kernel(
    const float* __restrict__ eps,
    const float* __restrict__ sigma2,
    const float4* __restrict__ c_prev4,
    const float* __restrict__ Wf_w, const float* __restrict__ Wf_b,
    const float* __restrict__ Uf_w, const float* __restrict__ Uf_b,
    const float* __restrict__ Wi_w, const float* __restrict__ Wi_b,
    const float* __restrict__ Ui_w, const float* __restrict__ Ui_b,
    const float* __restrict__ Wc_w, const float* __restrict__ Wc_b,
    const float* __restrict__ Uc_w, const float* __restrict__ Uc_b,
    const float* __restrict__ b_f, const float* __restrict__ b_i,
    const float* __restrict__ b_c,
    const float* __restrict__ w,
    const float* __restrict__ garch_w,
    const float* __restrict__ garch_b,
    float* __restrict__ out, int B)
{
    const int g  = threadIdx.x & 3;   // h-group: handles h = 4g..4g+3
    const int h0 = g * 4;

    // Loop-invariant coefficients, pre-scaled by 0.5 for the tanh identity.
    float Af[4], Bf[4], Cf[4], Ai[4], Bi[4], Ci[4], Ac[4], Bc[4], Cc[4];
    const float bf = __ldg(b_f), bi = __ldg(b_i), bc = __ldg(b_c);
    #pragma unroll
    for (int j = 0; j < 4; j++) {
        const int h = h0 + j;
        Af[j] = 0.5f * __ldg(Wf_w + h);
        Bf[j] = 0.5f * __ldg(Uf_w + h);
        Cf[j] = 0.5f * (__ldg(Wf_b + h) + __ldg(Uf_b + h) + bf);
        Ai[j] = 0.5f * __ldg(Wi_w + h);
        Bi[j] = 0.5f * __ldg(Ui_w + h);
        Ci[j] = 0.5f * (__ldg(Wi_b + h) + __ldg(Ui_b + h) + bi);
        Ac[j] = 0.5f * __ldg(Wc_w + h);
        Bc[j] = 0.5f * __ldg(Uc_w + h);
        Cc[j] = 0.5f * (__ldg(Wc_b + h) + __ldg(Uc_b + h) + bc);
    }

    const float gw0 = __ldg(garch_w + 0);
    const float gw1 = __ldg(garch_w + 1);
    const float gw2 = __ldg(garch_w + 2);
    const float gw3 = __ldg(garch_w + 3);
    const float gb  = __ldg(garch_b);
    const float wv  = __ldg(w) * (1.0f / 16.0f);  // fold mean's 1/16

    float*  __restrict__ out_sig = out;                  // sigma2_t : B
    float4* __restrict__ out_c4  = (float4*)(out + B);   // c_t      : B*16

    int r = (blockIdx.x * blockDim.x + threadIdx.x) >> 2;
    const int stride = (gridDim.x * blockDim.x) >> 2;

    #pragma unroll 2
    for (; r < B; r += stride) {
        const float  e  = __ldg(eps + r);
        const float  s  = __ldg(sigma2 + r);
        const float4 cp = __ldg(c_prev4 + r * 4 + g);

        float c[4];
        const float cpv[4] = {cp.x, cp.y, cp.z, cp.w};
        float thsum = 0.0f;
        #pragma unroll
        for (int j = 0; j < 4; j++) {
            const float f_t   = fmaf(0.5f, fast_tanh(fmaf(e, Af[j], fmaf(s, Bf[j], Cf[j]))), 0.5f);
            const float i_t   = fmaf(0.5f, fast_tanh(fmaf(e, Ai[j], fmaf(s, Bi[j], Ci[j]))), 0.5f);
            const float c_hat = fmaf(0.5f, fast_tanh(fmaf(e, Ac[j], fmaf(s, Bc[j], Cc[j]))), 0.5f);
            c[j] = fmaf(f_t, cpv[j], i_t * c_hat);
            thsum += fast_tanh(c[j]);
        }

        out_c4[r * 4 + g] = make_float4(c[0], c[1], c[2], c[3]);

        thsum += __shfl_xor_sync(0xffffffffu, thsum, 1);
        thsum += __shfl_xor_sync(0xffffffffu, thsum, 2);

        if (g == 0) {
            const float e2 = e * e;
            float o = fmaf(gw1, e2, fmaf(gw3, s, gw0 + gb));
            if (e < 0.0f) o = fmaf(gw2, e2, o);
            out_sig[r] = o * fmaf(wv, thsum, 1.0f);
        }
    }
}

extern "C" void kernel_launch(void* const* d_in, const int* in_sizes, int n_in,
                              void* d_out, int out_size) {
    // Two plausible input orderings:
    //  dict order (setup_inputs):     idx7 = Wi_w (size 16)
    //  signature order (reference):   idx7 = b_f  (size 1)
    const float* p[21];
    if (n_in >= 21 && in_sizes[7] == 1) {
        const int map[21] = {0, 1, 2,
                             3, 4, 5, 6,      // Wf_w Wf_b Uf_w Uf_b
                             8, 9, 10, 11,    // Wi_w Wi_b Ui_w Ui_b
                             13, 14, 15, 16,  // Wc_w Wc_b Uc_w Uc_b
                             7, 12, 17,       // b_f b_i b_c
                             18, 19, 20};     // w garch_w garch_b
        for (int i = 0; i < 21; i++) p[i] = (const float*)d_in[map[i]];
    } else {
        for (int i = 0; i < 21; i++) p[i] = (const float*)d_in[i];
    }

    const int B = in_sizes[0];
    float* out = (float*)d_out;

    // 4096 blocks x 128 threads = 524288 threads -> 131072 rows/sweep
    // -> exactly 16 iterations for B = 2M.
    garch_lstm_kernel<<<4096, 128>>>(
        p[0], p[1], (const float4*)p[2],
        p[3], p[4], p[5], p[6],
        p[7], p[8], p[9], p[10],
        p[11], p[12], p[13], p[14],
        p[15], p[16], p[17],
        p[18], p[19], p[20],
        out, B);
}

// round 3
// speedup vs baseline: 2.4487x; 1.2057x over previous
#include <cuda_runtime.h>

// GARCH-LSTM fused cell. B rows, H=16.
// Thread owns 4 h-values (g=lane&3) of one row. Software-pipelined: 4 rows'
// loads front-batched per iteration (12 LDGs in flight), streaming cache
// hints, then compute+store. sigmoid(x)=0.5+0.5*tanh(x/2), 0.5 pre-folded.

__device__ __forceinline__ float fast_tanh(float x) {
    float r;
    asm("tanh.approx.f32 %0, %1;" : "=f"(r) : "f"(x));
    return r;
}

#define BATCH 4

__global__ void __launch_bounds__(128)
garch_lstm_kernel(
    const float* __restrict__ eps,
    const float* __restrict__ sigma2,
    const float4* __restrict__ c_prev4,
    const float* __restrict__ Wf_w, const float* __restrict__ Wf_b,
    const float* __restrict__ Uf_w, const float* __restrict__ Uf_b,
    const float* __restrict__ Wi_w, const float* __restrict__ Wi_b,
    const float* __restrict__ Ui_w, const float* __restrict__ Ui_b,
    const float* __restrict__ Wc_w, const float* __restrict__ Wc_b,
    const float* __restrict__ Uc_w, const float* __restrict__ Uc_b,
    const float* __restrict__ b_f, const float* __restrict__ b_i,
    const float* __restrict__ b_c,
    const float* __restrict__ w,
    const float* __restrict__ garch_w,
    const float* __restrict__ garch_b,
    float* __restrict__ out, int B)
{
    const int g  = threadIdx.x & 3;   // h-group: handles h = 4g..4g+3
    const int h0 = g * 4;

    // Loop-invariant coefficients in registers, pre-scaled by 0.5.
    float Af[4], Bf[4], Cf[4], Ai[4], Bi[4], Ci[4], Ac[4], Bc[4], Cc[4];
    const float bfv = __ldg(b_f), biv = __ldg(b_i), bcv = __ldg(b_c);
    #pragma unroll
    for (int j = 0; j < 4; j++) {
        const int h = h0 + j;
        Af[j] = 0.5f * __ldg(Wf_w + h);
        Bf[j] = 0.5f * __ldg(Uf_w + h);
        Cf[j] = 0.5f * (__ldg(Wf_b + h) + __ldg(Uf_b + h) + bfv);
        Ai[j] = 0.5f * __ldg(Wi_w + h);
        Bi[j] = 0.5f * __ldg(Ui_w + h);
        Ci[j] = 0.5f * (__ldg(Wi_b + h) + __ldg(Ui_b + h) + biv);
        Ac[j] = 0.5f * __ldg(Wc_w + h);
        Bc[j] = 0.5f * __ldg(Uc_w + h);
        Cc[j] = 0.5f * (__ldg(Wc_b + h) + __ldg(Uc_b + h) + bcv);
    }

    const float gw0 = __ldg(garch_w + 0);
    const float gw1 = __ldg(garch_w + 1);
    const float gw2 = __ldg(garch_w + 2);
    const float gw3 = __ldg(garch_w + 3);
    const float gb  = __ldg(garch_b);
    const float wv  = __ldg(w) * (1.0f / 16.0f);

    float*  __restrict__ out_sig = out;                  // sigma2_t : B
    float4* __restrict__ out_c4  = (float4*)(out + B);   // c_t      : B*16

    const int stride = (gridDim.x * blockDim.x) >> 2;    // rows per sweep
    int r = (blockIdx.x * blockDim.x + threadIdx.x) >> 2;

    // Fast path: BATCH rows per iteration, loads front-batched.
    for (; r + (BATCH - 1) * stride < B; r += BATCH * stride) {
        float  e[BATCH], s[BATCH];
        float4 cp[BATCH];
        #pragma unroll
        for (int k = 0; k < BATCH; k++) {
            const int rk = r + k * stride;
            e[k]  = __ldcs(eps + rk);
            s[k]  = __ldcs(sigma2 + rk);
            cp[k] = __ldcs(c_prev4 + (size_t)rk * 4 + g);
        }

        #pragma unroll
        for (int k = 0; k < BATCH; k++) {
            const int rk = r + k * stride;
            const float cpv[4] = {cp[k].x, cp[k].y, cp[k].z, cp[k].w};
            float c[4];
            float thsum = 0.0f;
            #pragma unroll
            for (int j = 0; j < 4; j++) {
                const float f_t   = fmaf(0.5f, fast_tanh(fmaf(e[k], Af[j], fmaf(s[k], Bf[j], Cf[j]))), 0.5f);
                const float i_t   = fmaf(0.5f, fast_tanh(fmaf(e[k], Ai[j], fmaf(s[k], Bi[j], Ci[j]))), 0.5f);
                const float c_hat = fmaf(0.5f, fast_tanh(fmaf(e[k], Ac[j], fmaf(s[k], Bc[j], Cc[j]))), 0.5f);
                c[j] = fmaf(f_t, cpv[j], i_t * c_hat);
                thsum += fast_tanh(c[j]);
            }

            float4 cv = make_float4(c[0], c[1], c[2], c[3]);
            __stcs(out_c4 + (size_t)rk * 4 + g, cv);

            thsum += __shfl_xor_sync(0xffffffffu, thsum, 1);
            thsum += __shfl_xor_sync(0xffffffffu, thsum, 2);

            if (g == 0) {
                const float e2 = e[k] * e[k];
                const float ga = (e[k] < 0.0f) ? gw2 : 0.0f;
                float o = fmaf(gw1 + ga, e2, fmaf(gw3, s[k], gw0 + gb));
                __stcs(out_sig + rk, o * fmaf(wv, thsum, 1.0f));
            }
        }
    }

    // Tail (not taken for B = 2M with this grid, kept for generality).
    for (; r < B; r += stride) {
        const float  e  = __ldcs(eps + r);
        const float  s  = __ldcs(sigma2 + r);
        const float4 cp = __ldcs(c_prev4 + (size_t)r * 4 + g);
        const float cpv[4] = {cp.x, cp.y, cp.z, cp.w};
        float c[4];
        float thsum = 0.0f;
        #pragma unroll
        for (int j = 0; j < 4; j++) {
            const float f_t   = fmaf(0.5f, fast_tanh(fmaf(e, Af[j], fmaf(s, Bf[j], Cf[j]))), 0.5f);
            const float i_t   = fmaf(0.5f, fast_tanh(fmaf(e, Ai[j], fmaf(s, Bi[j], Ci[j]))), 0.5f);
            const float c_hat = fmaf(0.5f, fast_tanh(fmaf(e, Ac[j], fmaf(s, Bc[j], Cc[j]))), 0.5f);
            c[j] = fmaf(f_t, cpv[j], i_t * c_hat);
            thsum += fast_tanh(c[j]);
        }
        __stcs(out_c4 + (size_t)r * 4 + g, make_float4(c[0], c[1], c[2], c[3]));
        thsum += __shfl_xor_sync(0xffffffffu, thsum, 1);
        thsum += __shfl_xor_sync(0xffffffffu, thsum, 2);
        if (g == 0) {
            const float e2 = e * e;
            const float ga = (e < 0.0f) ? gw2 : 0.0f;
            float o = fmaf(gw1 + ga, e2, fmaf(gw3, s, gw0 + gb));
            __stcs(out_sig + r, o * fmaf(wv, thsum, 1.0f));
        }
    }
}

extern "C" void kernel_launch(void* const* d_in, const int* in_sizes, int n_in,
                              void* d_out, int out_size) {
    const float* p[21];
    if (n_in >= 21 && in_sizes[7] == 1) {
        // reference-signature order
        const int map[21] = {0, 1, 2,
                             3, 4, 5, 6,      // Wf_w Wf_b Uf_w Uf_b
                             8, 9, 10, 11,    // Wi_w Wi_b Ui_w Ui_b
                             13, 14, 15, 16,  // Wc_w Wc_b Uc_w Uc_b
                             7, 12, 17,       // b_f b_i b_c
                             18, 19, 20};     // w garch_w garch_b
        for (int i = 0; i < 21; i++) p[i] = (const float*)d_in[map[i]];
    } else {
        // setup_inputs dict order
        for (int i = 0; i < 21; i++) p[i] = (const float*)d_in[i];
    }

    const int B = in_sizes[0];
    float* out = (float*)d_out;

    // 2048 blocks x 128 threads -> 65536 rows/sweep -> 32 sweeps -> 8 outer
    // iterations of BATCH=4 for B = 2M. Persistent grid, no wave churn.
    garch_lstm_kernel<<<2048, 128>>>(
        p[0], p[1], (const float4*)p[2],
        p[3], p[4], p[5], p[6],
        p[7], p[8], p[9], p[10],
        p[11], p[12], p[13], p[14],
        p[15], p[16], p[17],
        p[18], p[19], p[20],
        out, B);
}